// round 6
// baseline (speedup 1.0000x reference)
#include <cuda_runtime.h>

// ---------------------------------------------------------------------------
// GNNMLP fused kernel, round 5: crossbar-pressure rebalance.
//  * k-packed f32x2 accumulators: acc = (sum_even_k, sum_odd_k) per output col
//    -> activation operand is a NATURAL (x_k,x_k+1) 8B broadcast (1 crossbar
//       cycle), no duplication, no packing MOVs. Halves added at epilogue.
//  * conv: 2 groups (12 rows) per warp amortize weight LDS.128 -> fma-bound
//  * MLP: ring-batched 8 groups per warp, type-fused layer1 -> weight loads
//    amortized 8-16x
//  * Wn1/Wn2/MW2/MW3 pre-transposed to (k,k+1)-pair layout in __device__
//    scratch by a prep kernel; streamed via LDG.128 (L2-resident)
//  * 12 warps x 384 thr, smem 219KB: Wp/Ws1/2 + MW1 + workspace
// ---------------------------------------------------------------------------

#define G_TOT   131072
#define THREADS 384
#define WARPS   12

typedef unsigned long long ull;

__device__ float g_wk[6 * 4096];   // kcp copies: Wn1,Wn2,MW2t0,MW2t1,MW3t0,MW3t1

// ---- helpers ---------------------------------------------------------------
__device__ __forceinline__ ull ldsbc64(unsigned a) {
    ull r; asm volatile("ld.shared.b64 %0,[%1];" : "=l"(r) : "r"(a)); return r;
}
__device__ __forceinline__ void lds128(ull& a, ull& b, unsigned ad) {
    asm volatile("ld.shared.v2.u64 {%0,%1},[%2];" : "=l"(a), "=l"(b) : "r"(ad));
}
__device__ __forceinline__ void sts64(unsigned a, float x, float y) {
    asm volatile("st.shared.v2.f32 [%0],{%1,%2};" :: "r"(a), "f"(x), "f"(y));
}
__device__ __forceinline__ void sts128(unsigned a, float x, float y, float z, float w) {
    asm volatile("st.shared.v4.f32 [%0],{%1,%2,%3,%4};"
                 :: "r"(a), "f"(x), "f"(y), "f"(z), "f"(w));
}
__device__ __forceinline__ ull f2fma(ull a, ull b, ull c) {
    ull d; asm("fma.rn.f32x2 %0,%1,%2,%3;" : "=l"(d) : "l"(a), "l"(b), "l"(c));
    return d;
}
__device__ __forceinline__ float2 upk(ull v) {
    float2 r; asm("mov.b64 {%0,%1},%2;" : "=f"(r.x), "=f"(r.y) : "l"(v)); return r;
}

// ---- SMEM layout (float offsets) ------------------------------------------
// kcp layout: float4 entry (kh*32+l) = {W[2kh][2l],W[2kh+1][2l],W[2kh][2l+1],W[2kh+1][2l+1]}
#define OFF_WP1  0
#define OFF_WS1  4096
#define OFF_WP2  8192
#define OFF_WS2  12288
#define OFF_MW1  16384        // t0 @16384, t1 @20480  (kcp)
#define OFF_MISC 24576
//  MISC: +0 bp1 +64 b1 +128 bp2 +192 b2 +256 Mb1[2][64] +384 Mb2 +512 Mb3
//        +640 MW4[2][64][2] (256) +896 Mb4[4]
#define OFF_WS_  25600
#define WARP_WS  2432         // OBS 768 (XB aliases first 512) | NB 128 | RES 512 | XA0 512 | XA1 512
#define SMEM_FLOATS (OFF_WS_ + WARPS * WARP_WS)   // 54784
#define SMEM_BYTES  (SMEM_FLOATS * 4)             // 219136

struct Params {
    const float *obs, *Wp1, *bp1, *Ws1, *Wn1, *b1;
    const float *Wp2, *bp2, *Ws2, *Wn2, *b2;
    const float *MW1, *Mb1, *MW2, *Mb2, *MW3, *Mb3, *MW4, *Mb4;
    float *out;
    int ch8;
};

extern __shared__ float smem[];

__device__ __forceinline__ void cp4(float* dst, const float* src, int n) {
    for (int i = threadIdx.x; i < (n >> 2); i += THREADS)
        ((float4*)dst)[i] = ((const float4*)src)[i];
}
// row-major 64x64 -> kcp
__device__ __forceinline__ void cp_kcp(float* dst, const float* src) {
    float4* d4 = (float4*)dst;
    for (int j = threadIdx.x; j < 1024; j += THREADS) {
        int kh = j >> 5, l = j & 31;
        d4[j] = make_float4(src[2 * kh * 64 + 2 * l], src[(2 * kh + 1) * 64 + 2 * l],
                            src[2 * kh * 64 + 2 * l + 1], src[(2 * kh + 1) * 64 + 2 * l + 1]);
    }
}

// ---- prep kernel: build kcp copies of Wn1,Wn2,MW2,MW3 in g_wk --------------
__global__ void prep_kernel(const float* Wn1, const float* Wn2,
                            const float* MW2, const float* MW3)
{
    int j = blockIdx.x * blockDim.x + threadIdx.x;
    if (j >= 6 * 1024) return;
    int m = j >> 10, e = j & 1023;
    int kh = e >> 5, l = e & 31;
    const float* src;
    switch (m) {
        case 0: src = Wn1; break;
        case 1: src = Wn2; break;
        case 2: src = MW2; break;
        case 3: src = MW2 + 4096; break;
        case 4: src = MW3; break;
        default: src = MW3 + 4096; break;
    }
    ((float4*)(g_wk + m * 4096))[e] =
        make_float4(src[2 * kh * 64 + 2 * l], src[(2 * kh + 1) * 64 + 2 * l],
                    src[2 * kh * 64 + 2 * l + 1], src[(2 * kh + 1) * 64 + 2 * l + 1]);
}

// ---- one SAGE-pool conv, 2 groups (12 rows) --------------------------------
// ROWS/NB/RES are smem byte addresses; lane owns output cols {2l, 2l+1}.
template<bool FIRST>
__device__ __forceinline__ void conv2g(unsigned ROWS, unsigned NB, unsigned RESs,
                                       unsigned WPA, unsigned WSA,
                                       const float* __restrict__ wnk,
                                       const float* misc, int bP, int bB, int lane)
{
    ull aP[12][2], aS[12][2];
    #pragma unroll
    for (int r = 0; r < 12; r++) { aP[r][0] = aP[r][1] = aS[r][0] = aS[r][1] = 0ull; }

    const unsigned wp = WPA + lane * 16, ws = WSA + lane * 16;
    #pragma unroll 2
    for (int kh = 0; kh < 32; kh++) {
        ull wp0, wp1, ws0, ws1;
        lds128(wp0, wp1, wp + kh * 512);
        lds128(ws0, ws1, ws + kh * 512);
        #pragma unroll
        for (int r = 0; r < 12; r++) {
            ull x = ldsbc64(ROWS + r * 256 + kh * 8);   // (x_k, x_k+1) broadcast
            aP[r][0] = f2fma(x, wp0, aP[r][0]);
            aP[r][1] = f2fma(x, wp1, aP[r][1]);
            aS[r][0] = f2fma(x, ws0, aS[r][0]);
            aS[r][1] = f2fma(x, ws1, aS[r][1]);
        }
    }

    // neigh = max_r relu(p_r + bp); relu folded via 0-init
    float bp0 = misc[bP + 2 * lane], bp1v = misc[bP + 2 * lane + 1];
    #pragma unroll
    for (int g = 0; g < 2; g++) {
        float m0 = 0.f, m1 = 0.f;
        #pragma unroll
        for (int r = g * 6; r < g * 6 + 6; r++) {
            float2 e0 = upk(aP[r][0]), e1 = upk(aP[r][1]);
            m0 = fmaxf(m0, e0.x + e0.y + bp0);
            m1 = fmaxf(m1, e1.x + e1.y + bp1v);
        }
        sts64(NB + g * 256 + lane * 8, m0, m1);
    }
    __syncwarp();

    // nn = neigh @ Wn  (Wn in kcp layout, streamed from global scratch)
    ull aN[2][2] = {{0ull, 0ull}, {0ull, 0ull}};
    const ulonglong2* wn2 = (const ulonglong2*)wnk + lane;
    #pragma unroll 4
    for (int kh = 0; kh < 32; kh++) {
        ulonglong2 w = wn2[kh * 32];                    // LDG.128
        ull x0 = ldsbc64(NB + kh * 8);
        ull x1 = ldsbc64(NB + 256 + kh * 8);
        aN[0][0] = f2fma(x0, w.x, aN[0][0]);
        aN[0][1] = f2fma(x0, w.y, aN[0][1]);
        aN[1][0] = f2fma(x1, w.x, aN[1][0]);
        aN[1][1] = f2fma(x1, w.y, aN[1][1]);
    }
    float bb0 = misc[bB + 2 * lane], bb1 = misc[bB + 2 * lane + 1];
    float2 e;
    e = upk(aN[0][0]); float n00 = e.x + e.y + bb0;
    e = upk(aN[0][1]); float n01 = e.x + e.y + bb1;
    e = upk(aN[1][0]); float n10 = e.x + e.y + bb0;
    e = upk(aN[1][1]); float n11 = e.x + e.y + bb1;

    if (FIRST) {
        #pragma unroll
        for (int r = 0; r < 12; r++) {
            float nx = (r < 6) ? n00 : n10, ny = (r < 6) ? n01 : n11;
            float2 e0 = upk(aS[r][0]), e1 = upk(aS[r][1]);
            sts64(ROWS + r * 256 + lane * 8,
                  tanhf(e0.x + e0.y + nx), tanhf(e1.x + e1.y + ny));
        }
    } else {
        #pragma unroll
        for (int g = 0; g < 2; g++) {
            float s0 = 0.f, s1 = 0.f;
            #pragma unroll
            for (int r = g * 6; r < g * 6 + 6; r++) {
                float2 e0 = upk(aS[r][0]), e1 = upk(aS[r][1]);
                s0 += e0.x + e0.y; s1 += e1.x + e1.y;
            }
            sts64(RESs + g * 256 + lane * 8,
                  s0 * (1.f / 6.f) + (g ? n10 : n00),
                  s1 * (1.f / 6.f) + (g ? n11 : n01));
        }
    }
    __syncwarp();
}

__global__ void __launch_bounds__(THREADS, 1) gnn_kernel(Params P)
{
    cp_kcp(smem + OFF_WP1, P.Wp1);
    cp_kcp(smem + OFF_WS1, P.Ws1);
    cp_kcp(smem + OFF_WP2, P.Wp2);
    cp_kcp(smem + OFF_WS2, P.Ws2);
    cp_kcp(smem + OFF_MW1,        P.MW1);
    cp_kcp(smem + OFF_MW1 + 4096, P.MW1 + 4096);
    cp4(smem + OFF_MISC +   0, P.bp1, 64);
    cp4(smem + OFF_MISC +  64, P.b1,  64);
    cp4(smem + OFF_MISC + 128, P.bp2, 64);
    cp4(smem + OFF_MISC + 192, P.b2,  64);
    cp4(smem + OFF_MISC + 256, P.Mb1, 128);
    cp4(smem + OFF_MISC + 384, P.Mb2, 128);
    cp4(smem + OFF_MISC + 512, P.Mb3, 128);
    cp4(smem + OFF_MISC + 640, P.MW4, 256);
    cp4(smem + OFF_MISC + 896, P.Mb4, 4);
    __syncthreads();

    const int lane = threadIdx.x & 31;
    const int warp = threadIdx.x >> 5;
    const float* misc = smem + OFF_MISC;

    const unsigned sb  = (unsigned)__cvta_generic_to_shared(smem);
    const unsigned wsA = sb + (OFF_WS_ + warp * WARP_WS) * 4;
    const unsigned OBS = wsA;                  // [12][64] natural (byte)
    const unsigned XB  = wsA;                  // alias (dead OBS during MLP)
    const unsigned NB  = wsA + 768 * 4;        // [2][64]
    const unsigned RES = wsA + 896 * 4;        // ring [8][64]
    const unsigned XA0 = wsA + 1408 * 4;       // [8][64]
    const unsigned XA1 = wsA + 1920 * 4;
    const unsigned WP1 = sb + OFF_WP1 * 4, WS1 = sb + OFF_WS1 * 4;
    const unsigned WP2 = sb + OFF_WP2 * 4, WS2 = sb + OFF_WS2 * 4;
    const unsigned MW1A = sb + OFF_MW1 * 4;

    const int wg   = blockIdx.x * WARPS + warp;
    const int base = wg * P.ch8;
    const int iters = P.ch8 >> 1;

    for (int j = 0; j < iters; j++) {
        const int g0 = base + 2 * j, g1 = g0 + 1;

        // stage obs (natural layout), zero-fill invalid groups
        {
            const float4* s0 = (const float4*)(P.obs + (size_t)g0 * 384);
            const float4* s1 = (const float4*)(P.obs + (size_t)g1 * 384);
            const float4 z = make_float4(0.f, 0.f, 0.f, 0.f);
            #pragma unroll
            for (int i = 0; i < 3; i++) {
                int m = lane + 32 * i;
                float4 a = (g0 < G_TOT) ? s0[m] : z;
                float4 b = (g1 < G_TOT) ? s1[m] : z;
                sts128(OBS + m * 16, a.x, a.y, a.z, a.w);
                sts128(OBS + 1536 + m * 16, b.x, b.y, b.z, b.w);
            }
        }
        __syncwarp();

        const unsigned RESs = RES + ((j & 3) * 2) * 256;
        conv2g<true >(OBS, NB, RESs, WP1, WS1, g_wk,        misc,   0,  64, lane);
        conv2g<false>(OBS, NB, RESs, WP2, WS2, g_wk + 4096, misc, 128, 192, lane);

        if ((j & 3) == 3) {
            // ---- MLP on 8 ring groups ----
            const int gbase = base + ((j & ~3) * 2);

            // L1: fused over both types (shared RES broadcast)
            ull a1[8][2][2];
            #pragma unroll
            for (int g = 0; g < 8; g++)
                a1[g][0][0] = a1[g][0][1] = a1[g][1][0] = a1[g][1][1] = 0ull;
            const unsigned w1t0 = MW1A + lane * 16, w1t1 = MW1A + 16384 + lane * 16;
            #pragma unroll 2
            for (int kh = 0; kh < 32; kh++) {
                ull wa0, wa1, wb0, wb1;
                lds128(wa0, wa1, w1t0 + kh * 512);
                lds128(wb0, wb1, w1t1 + kh * 512);
                #pragma unroll
                for (int g = 0; g < 8; g++) {
                    ull x = ldsbc64(RES + g * 256 + kh * 8);
                    a1[g][0][0] = f2fma(x, wa0, a1[g][0][0]);
                    a1[g][0][1] = f2fma(x, wa1, a1[g][0][1]);
                    a1[g][1][0] = f2fma(x, wb0, a1[g][1][0]);
                    a1[g][1][1] = f2fma(x, wb1, a1[g][1][1]);
                }
            }
            {
                float m00 = misc[256 + 2 * lane],      m01 = misc[256 + 2 * lane + 1];
                float m10 = misc[256 + 64 + 2 * lane], m11 = misc[256 + 64 + 2 * lane + 1];
                #pragma unroll
                for (int g = 0; g < 8; g++) {
                    float2 e0 = upk(a1[g][0][0]), e1 = upk(a1[g][0][1]);
                    sts64(XA0 + g * 256 + lane * 8,
                          fmaxf(e0.x + e0.y + m00, 0.f), fmaxf(e1.x + e1.y + m01, 0.f));
                    e0 = upk(a1[g][1][0]); e1 = upk(a1[g][1][1]);
                    sts64(XA1 + g * 256 + lane * 8,
                          fmaxf(e0.x + e0.y + m10, 0.f), fmaxf(e1.x + e1.y + m11, 0.f));
                }
            }
            __syncwarp();

            float hA[8], hB[8];
            #pragma unroll
            for (int t = 0; t < 2; t++) {
                const unsigned XAt = t ? XA1 : XA0;
                // L2: XA_t -> XB
                ull a2[8][2];
                #pragma unroll
                for (int g = 0; g < 8; g++) a2[g][0] = a2[g][1] = 0ull;
                const ulonglong2* w2 = (const ulonglong2*)(g_wk + 8192 + t * 4096) + lane;
                #pragma unroll 2
                for (int kh = 0; kh < 32; kh++) {
                    ulonglong2 w = w2[kh * 32];
                    #pragma unroll
                    for (int g = 0; g < 8; g++) {
                        ull x = ldsbc64(XAt + g * 256 + kh * 8);
                        a2[g][0] = f2fma(x, w.x, a2[g][0]);
                        a2[g][1] = f2fma(x, w.y, a2[g][1]);
                    }
                }
                {
                    float b0 = misc[384 + t * 64 + 2 * lane], b1 = misc[384 + t * 64 + 2 * lane + 1];
                    #pragma unroll
                    for (int g = 0; g < 8; g++) {
                        float2 e0 = upk(a2[g][0]), e1 = upk(a2[g][1]);
                        sts64(XB + g * 256 + lane * 8,
                              fmaxf(e0.x + e0.y + b0, 0.f), fmaxf(e1.x + e1.y + b1, 0.f));
                    }
                }
                __syncwarp();

                // L3: XB -> regs
                ull a3[8][2];
                #pragma unroll
                for (int g = 0; g < 8; g++) a3[g][0] = a3[g][1] = 0ull;
                const ulonglong2* w3 = (const ulonglong2*)(g_wk + 16384 + t * 4096) + lane;
                #pragma unroll 2
                for (int kh = 0; kh < 32; kh++) {
                    ulonglong2 w = w3[kh * 32];
                    #pragma unroll
                    for (int g = 0; g < 8; g++) {
                        ull x = ldsbc64(XB + g * 256 + kh * 8);
                        a3[g][0] = f2fma(x, w.x, a3[g][0]);
                        a3[g][1] = f2fma(x, w.y, a3[g][1]);
                    }
                }
                // head: relu + [64]->2 warp reduction + tanh
                float4 w4 = *(const float4*)(misc + 640 + t * 128 + 4 * lane);
                float b30 = misc[512 + t * 64 + 2 * lane], b31 = misc[512 + t * 64 + 2 * lane + 1];
                float b40 = misc[896 + t * 2], b41 = misc[896 + t * 2 + 1];
                #pragma unroll
                for (int g = 0; g < 8; g++) {
                    float2 e0 = upk(a3[g][0]), e1 = upk(a3[g][1]);
                    float v0 = fmaxf(e0.x + e0.y + b30, 0.f);
                    float v1 = fmaxf(e1.x + e1.y + b31, 0.f);
                    float s0 = v0 * w4.x + v1 * w4.z;
                    float s1 = v0 * w4.y + v1 * w4.w;
                    #pragma unroll
                    for (int off = 16; off; off >>= 1) {
                        s0 += __shfl_xor_sync(0xffffffffu, s0, off);
                        s1 += __shfl_xor_sync(0xffffffffu, s1, off);
                    }
                    float r0 = tanhf(s0 + b40), r1 = tanhf(s1 + b41);
                    if (t == 0) { hA[g] = r0; hB[g] = r1; }
                    else {
                        int go = gbase + g;
                        if (go < G_TOT && lane < 3) {
                            float A = hA[g], B = hB[g];
                            float4 v = (lane < 2) ? make_float4(A, B, A, B)
                                                  : make_float4(A, B, r0, r1);
                            ((float4*)(P.out + (size_t)go * 12))[lane] = v;
                        }
                    }
                }
                __syncwarp();   // XB reused by t=1
            }
        }
    }
}

extern "C" void kernel_launch(void* const* d_in, const int* in_sizes, int n_in,
                              void* d_out, int out_size)
{
    (void)in_sizes; (void)n_in; (void)out_size;
    Params P;
    P.obs = (const float*)d_in[0];
    P.Wp1 = (const float*)d_in[1];  P.bp1 = (const float*)d_in[2];
    P.Ws1 = (const float*)d_in[3];  P.Wn1 = (const float*)d_in[4];
    P.b1  = (const float*)d_in[5];
    P.Wp2 = (const float*)d_in[6];  P.bp2 = (const float*)d_in[7];
    P.Ws2 = (const float*)d_in[8];  P.Wn2 = (const float*)d_in[9];
    P.b2  = (const float*)d_in[10];
    P.MW1 = (const float*)d_in[11]; P.Mb1 = (const float*)d_in[12];
    P.MW2 = (const float*)d_in[13]; P.Mb2 = (const float*)d_in[14];
    P.MW3 = (const float*)d_in[15]; P.Mb3 = (const float*)d_in[16];
    P.MW4 = (const float*)d_in[17]; P.Mb4 = (const float*)d_in[18];
    P.out = (float*)d_out;

    int dev = 0, nsm = 148;
    cudaGetDevice(&dev);
    cudaDeviceGetAttribute(&nsm, cudaDevAttrMultiProcessorCount, dev);

    // groups per warp, rounded to a multiple of 8 (MLP ring size)
    int nw = nsm * WARPS;
    int ch8 = ((G_TOT + nw * 8 - 1) / (nw * 8)) * 8;
    P.ch8 = ch8;

    prep_kernel<<<(6 * 1024 + 255) / 256, 256>>>(P.Wn1, P.Wn2, P.MW2, P.MW3);

    cudaFuncSetAttribute(gnn_kernel, cudaFuncAttributeMaxDynamicSharedMemorySize,
                         SMEM_BYTES);
    gnn_kernel<<<nsm, THREADS, SMEM_BYTES>>>(P);
}

// round 7
// speedup vs baseline: 1.6882x; 1.6882x over previous
#include <cuda_runtime.h>

// ---------------------------------------------------------------------------
// GNNMLP fused kernel, round 6.
//   conv: R4's dup-layout idiom (verified clean fma count), 2 groups/warp
//   MLP:  batched over 4 groups (ring), weights streamed from __device__
//         scratch (prep kernel builds interleaved layout), head from regs
//   16 warps / 512 threads, smem 217KB, all hot-loop addresses base+imm
// ---------------------------------------------------------------------------

#define G_TOT   131072
#define THREADS 512
#define WARPS   16

typedef unsigned long long ull;

__device__ float g_wk[8 * 4096];  // interleaved: Wn1,Wn2,MW1t0,MW1t1,MW2t0,MW2t1,MW3t0,MW3t1

// ---- helpers ---------------------------------------------------------------
__device__ __forceinline__ float2 upk(ull v) {
    float2 r; asm("mov.b64 {%0,%1}, %2;" : "=f"(r.x), "=f"(r.y) : "l"(v)); return r;
}
__device__ __forceinline__ ull f2fma(ull a, ull b, ull c) {
    ull d; asm("fma.rn.f32x2 %0, %1, %2, %3;" : "=l"(d) : "l"(a), "l"(b), "l"(c));
    return d;
}
__device__ __forceinline__ ull f2add(ull a, ull b) {
    ull d; asm("add.rn.f32x2 %0, %1, %2;" : "=l"(d) : "l"(a), "l"(b)); return d;
}
__device__ __forceinline__ void lds128(ull& a, ull& b, unsigned addr) {
    asm volatile("ld.shared.v2.u64 {%0,%1}, [%2];" : "=l"(a), "=l"(b) : "r"(addr));
}
__device__ __forceinline__ void sts128(unsigned a, float x, float y, float z, float w) {
    asm volatile("st.shared.v4.f32 [%0], {%1,%2,%3,%4};"
                 :: "r"(a), "f"(x), "f"(y), "f"(z), "f"(w));
}
__device__ __forceinline__ void ldg2u64(ull& a, ull& b, const float* p) {
    asm volatile("ld.global.nc.v2.u64 {%0,%1}, [%2];" : "=l"(a), "=l"(b) : "l"(p));
}

// ---- SMEM layout (float offsets) ------------------------------------------
// Interleaved weight layout: float4 j=(kh*32+cp) =
//   (W[2kh][2cp], W[2kh][2cp+1], W[2kh+1][2cp], W[2kh+1][2cp+1])
#define OFF_WP1  0
#define OFF_WS1  4096
#define OFF_WP2  8192
#define OFF_WS2  12288
#define OFF_MISC 16384
//  MISC: +0 bp1 +64 b1 +128 bp2 +192 b2 +256 Mb1[128] +384 Mb2[128]
//        +512 Mb3[128] +640 MW4[2][64][2] +896 Mb4[4]
#define OFF_WS_  17408
#define WARP_WS  2304     // OBS dup [12][128] =1536 | NB dup [2][128]=256 | RES dup [4][128]=512
#define SMEM_FLOATS (OFF_WS_ + WARPS * WARP_WS)   // 54272
#define SMEM_BYTES  (SMEM_FLOATS * 4)             // 217088 < 232448

struct Params {
    const float *obs, *Wp1, *bp1, *Ws1, *Wn1, *b1;
    const float *Wp2, *bp2, *Ws2, *Wn2, *b2;
    const float *MW1, *Mb1, *MW2, *Mb2, *MW3, *Mb3, *MW4, *Mb4;
    float *out;
    int ch4;
};

extern __shared__ float smem[];

__device__ __forceinline__ void cp4(float* dst, const float* src, int n) {
    for (int i = threadIdx.x; i < (n >> 2); i += THREADS)
        ((float4*)dst)[i] = ((const float4*)src)[i];
}
// interleave one 64x64 row-major matrix into dst (smem)
__device__ __forceinline__ void cp_i(float* dst, const float* src) {
    const float2* s2 = (const float2*)src;
    float4* d4 = (float4*)dst;
    for (int j = threadIdx.x; j < 1024; j += THREADS) {
        int kh = j >> 5, cp = j & 31;
        float2 a = s2[(2 * kh) * 32 + cp];
        float2 b = s2[(2 * kh + 1) * 32 + cp];
        d4[j] = make_float4(a.x, a.y, b.x, b.y);
    }
}

// ---- prep kernel: interleaved copies of Wn1,Wn2,MW1,MW2,MW3 into g_wk ------
__global__ void prep_kernel(const float* Wn1, const float* Wn2, const float* MW1,
                            const float* MW2, const float* MW3)
{
    int j = blockIdx.x * blockDim.x + threadIdx.x;
    if (j >= 8 * 1024) return;
    int m = j >> 10, e = j & 1023;
    int kh = e >> 5, cp = e & 31;
    const float* src;
    switch (m) {
        case 0: src = Wn1; break;
        case 1: src = Wn2; break;
        case 2: src = MW1; break;
        case 3: src = MW1 + 4096; break;
        case 4: src = MW2; break;
        case 5: src = MW2 + 4096; break;
        case 6: src = MW3; break;
        default: src = MW3 + 4096; break;
    }
    const float2* s2 = (const float2*)src;
    float2 a = s2[(2 * kh) * 32 + cp];
    float2 b = s2[(2 * kh + 1) * 32 + cp];
    ((float4*)(g_wk + m * 4096))[e] = make_float4(a.x, a.y, b.x, b.y);
}

// ---- one SAGE-pool conv, 2 groups (12 dup rows) ----------------------------
// ROWS: dup [12][128fl], row r at +r*512B, k-pair kh at +kh*16B.
// Lane owns output cols {2l, 2l+1}.
template<bool FIRST>
__device__ __forceinline__ void conv2g(unsigned ROWS, unsigned NB, unsigned RESs,
                                       unsigned WPA, unsigned WSA,
                                       const float* __restrict__ wng,
                                       const float* misc, int bP, int bB, int lane)
{
    ull aP[12], aS[12];
    ull bpv = *(const ull*)(misc + bP + 2 * lane);
    #pragma unroll
    for (int r = 0; r < 12; r++) { aP[r] = bpv; aS[r] = 0ull; }

    const unsigned wp = WPA + lane * 16, ws = WSA + lane * 16;
    #pragma unroll 4
    for (int kh = 0; kh < 32; kh++) {
        ull wp0, wp1, ws0, ws1;
        lds128(wp0, wp1, wp + kh * 512);
        lds128(ws0, ws1, ws + kh * 512);
        #pragma unroll
        for (int r = 0; r < 12; r++) {
            ull b0, b1;                                  // (x,x),(x',x') bc
            lds128(b0, b1, ROWS + r * 512 + kh * 16);
            aP[r] = f2fma(b1, wp1, f2fma(b0, wp0, aP[r]));
            aS[r] = f2fma(b1, ws1, f2fma(b0, ws0, aS[r]));
        }
    }

    // neigh = max over 6 agents of relu(p); relu folded via 0-init
    #pragma unroll
    for (int g = 0; g < 2; g++) {
        float mx = 0.f, my = 0.f;
        #pragma unroll
        for (int r = g * 6; r < g * 6 + 6; r++) {
            float2 p = upk(aP[r]);
            mx = fmaxf(mx, p.x); my = fmaxf(my, p.y);
        }
        sts128(NB + g * 512 + lane * 16, mx, mx, my, my);
    }
    __syncwarp();

    // nn = neigh @ Wn (interleaved layout streamed from g_wk, L1-resident)
    ull nn0 = 0ull, nn1 = 0ull;
    const float* wnp = wng + lane * 4;
    #pragma unroll 4
    for (int kh = 0; kh < 32; kh++) {
        ull w0, w1;
        ldg2u64(w0, w1, wnp + kh * 128);
        ull b0, b1;
        lds128(b0, b1, NB + kh * 16);
        nn0 = f2fma(b1, w1, f2fma(b0, w0, nn0));
        lds128(b0, b1, NB + 512 + kh * 16);
        nn1 = f2fma(b1, w1, f2fma(b0, w0, nn1));
    }
    ull bbv = *(const ull*)(misc + bB + 2 * lane);
    float2 n0 = upk(f2add(nn0, bbv));
    float2 n1 = upk(f2add(nn1, bbv));

    if (FIRST) {
        #pragma unroll
        for (int r = 0; r < 12; r++) {
            float2 s = upk(aS[r]);
            float nx = (r < 6) ? n0.x : n1.x, ny = (r < 6) ? n0.y : n1.y;
            float v0 = tanhf(s.x + nx);
            float v1 = tanhf(s.y + ny);
            sts128(ROWS + r * 512 + lane * 16, v0, v0, v1, v1);
        }
    } else {
        #pragma unroll
        for (int g = 0; g < 2; g++) {
            ull t = aS[g * 6];
            #pragma unroll
            for (int r = g * 6 + 1; r < g * 6 + 6; r++) t = f2add(t, aS[r]);
            float2 s = upk(t);
            float v0 = s.x * (1.f / 6.f) + (g ? n1.x : n0.x);
            float v1 = s.y * (1.f / 6.f) + (g ? n1.y : n0.y);
            sts128(RESs + g * 512 + lane * 16, v0, v0, v1, v1);
        }
    }
    __syncwarp();
}

__global__ void __launch_bounds__(THREADS, 1) gnn_kernel(Params P)
{
    cp_i(smem + OFF_WP1, P.Wp1);
    cp_i(smem + OFF_WS1, P.Ws1);
    cp_i(smem + OFF_WP2, P.Wp2);
    cp_i(smem + OFF_WS2, P.Ws2);
    cp4(smem + OFF_MISC +   0, P.bp1, 64);
    cp4(smem + OFF_MISC +  64, P.b1,  64);
    cp4(smem + OFF_MISC + 128, P.bp2, 64);
    cp4(smem + OFF_MISC + 192, P.b2,  64);
    cp4(smem + OFF_MISC + 256, P.Mb1, 128);
    cp4(smem + OFF_MISC + 384, P.Mb2, 128);
    cp4(smem + OFF_MISC + 512, P.Mb3, 128);
    cp4(smem + OFF_MISC + 640, P.MW4, 256);
    cp4(smem + OFF_MISC + 896, P.Mb4, 4);
    __syncthreads();

    const int lane = threadIdx.x & 31;
    const int warp = threadIdx.x >> 5;
    const float* misc = smem + OFF_MISC;

    const unsigned sb  = (unsigned)__cvta_generic_to_shared(smem);
    const unsigned wsA = sb + (OFF_WS_ + warp * WARP_WS) * 4;
    const unsigned OBS = wsA;                  // dup [12][128] (6144 B)
    const unsigned XA  = wsA;                  // alias: dup [4][128] (2048 B)
    const unsigned XB  = wsA + 2048;           // alias: dup [4][128]
    const unsigned NB  = wsA + 1536 * 4;       // dup [2][128]
    const unsigned RES = wsA + 1792 * 4;       // ring dup [4][128]
    const unsigned WP1 = sb + OFF_WP1 * 4, WS1 = sb + OFF_WS1 * 4;
    const unsigned WP2 = sb + OFF_WP2 * 4, WS2 = sb + OFF_WS2 * 4;

    const int wg   = blockIdx.x * WARPS + warp;
    const int base = wg * P.ch4;
    const int iters = P.ch4 >> 1;

    for (int j = 0; j < iters; j++) {
        const int g0 = base + 2 * j, g1 = g0 + 1;

        // stage obs duplicated: float2 (a,b) -> (a,a,b,b)
        {
            const float2* s0 = (const float2*)(P.obs + (size_t)g0 * 384);
            const float2* s1 = (const float2*)(P.obs + (size_t)g1 * 384);
            const float2 z = make_float2(0.f, 0.f);
            #pragma unroll
            for (int i = 0; i < 6; i++) {
                int m = lane + 32 * i;
                float2 a = (g0 < G_TOT) ? s0[m] : z;
                float2 b = (g1 < G_TOT) ? s1[m] : z;
                sts128(OBS + m * 16, a.x, a.x, a.y, a.y);
                sts128(OBS + 3072 + m * 16, b.x, b.x, b.y, b.y);
            }
        }
        __syncwarp();

        const unsigned RESs = RES + (j & 1) * 1024;
        conv2g<true >(OBS, NB, RESs, WP1, WS1, g_wk,        misc,   0,  64, lane);
        conv2g<false>(OBS, NB, RESs, WP2, WS2, g_wk + 4096, misc, 128, 192, lane);

        if (j & 1) {
            // ---- MLP on 4 ring groups ----
            const int gbase = base + 2 * (j - 1);
            float hA[4], hB[4];

            #pragma unroll
            for (int t = 0; t < 2; t++) {
                // L1: RES -> XA
                ull a1[4];
                ull b1v = *(const ull*)(misc + 256 + t * 64 + 2 * lane);
                #pragma unroll
                for (int g = 0; g < 4; g++) a1[g] = b1v;
                const float* w1p = g_wk + (2 + t) * 4096 + lane * 4;
                #pragma unroll 4
                for (int kh = 0; kh < 32; kh++) {
                    ull w0, w1;
                    ldg2u64(w0, w1, w1p + kh * 128);
                    #pragma unroll
                    for (int g = 0; g < 4; g++) {
                        ull b0, b1;
                        lds128(b0, b1, RES + g * 512 + kh * 16);
                        a1[g] = f2fma(b1, w1, f2fma(b0, w0, a1[g]));
                    }
                }
                #pragma unroll
                for (int g = 0; g < 4; g++) {
                    float2 v = upk(a1[g]);
                    float r0 = fmaxf(v.x, 0.f), r1 = fmaxf(v.y, 0.f);
                    sts128(XA + g * 512 + lane * 16, r0, r0, r1, r1);
                }
                __syncwarp();

                // L2: XA -> XB
                ull a2[4];
                ull b2v = *(const ull*)(misc + 384 + t * 64 + 2 * lane);
                #pragma unroll
                for (int g = 0; g < 4; g++) a2[g] = b2v;
                const float* w2p = g_wk + (4 + t) * 4096 + lane * 4;
                #pragma unroll 4
                for (int kh = 0; kh < 32; kh++) {
                    ull w0, w1;
                    ldg2u64(w0, w1, w2p + kh * 128);
                    #pragma unroll
                    for (int g = 0; g < 4; g++) {
                        ull b0, b1;
                        lds128(b0, b1, XA + g * 512 + kh * 16);
                        a2[g] = f2fma(b1, w1, f2fma(b0, w0, a2[g]));
                    }
                }
                #pragma unroll
                for (int g = 0; g < 4; g++) {
                    float2 v = upk(a2[g]);
                    float r0 = fmaxf(v.x, 0.f), r1 = fmaxf(v.y, 0.f);
                    sts128(XB + g * 512 + lane * 16, r0, r0, r1, r1);
                }
                __syncwarp();

                // L3: XB -> regs, then head directly from registers
                ull a3[4];
                ull b3v = *(const ull*)(misc + 512 + t * 64 + 2 * lane);
                #pragma unroll
                for (int g = 0; g < 4; g++) a3[g] = b3v;
                const float* w3p = g_wk + (6 + t) * 4096 + lane * 4;
                #pragma unroll 4
                for (int kh = 0; kh < 32; kh++) {
                    ull w0, w1;
                    ldg2u64(w0, w1, w3p + kh * 128);
                    #pragma unroll
                    for (int g = 0; g < 4; g++) {
                        ull b0, b1;
                        lds128(b0, b1, XB + g * 512 + kh * 16);
                        a3[g] = f2fma(b1, w1, f2fma(b0, w0, a3[g]));
                    }
                }
                float4 w4 = *(const float4*)(misc + 640 + t * 128 + 4 * lane);
                float b40 = misc[896 + t * 2], b41 = misc[896 + t * 2 + 1];
                #pragma unroll
                for (int g = 0; g < 4; g++) {
                    float2 v = upk(a3[g]);
                    float v0 = fmaxf(v.x, 0.f), v1 = fmaxf(v.y, 0.f);
                    float s0 = v0 * w4.x + v1 * w4.z;
                    float s1 = v0 * w4.y + v1 * w4.w;
                    #pragma unroll
                    for (int off = 16; off; off >>= 1) {
                        s0 += __shfl_xor_sync(0xffffffffu, s0, off);
                        s1 += __shfl_xor_sync(0xffffffffu, s1, off);
                    }
                    float r0 = tanhf(s0 + b40), r1 = tanhf(s1 + b41);
                    if (t == 0) { hA[g] = r0; hB[g] = r1; }
                    else {
                        int go = gbase + g;
                        if (go < G_TOT && lane < 3) {
                            float A = hA[g], B = hB[g];
                            float4 v4 = (lane < 2) ? make_float4(A, B, A, B)
                                                   : make_float4(A, B, r0, r1);
                            ((float4*)(P.out + (size_t)go * 12))[lane] = v4;
                        }
                    }
                }
                __syncwarp();   // XA/XB reused by t=1
            }
        }
    }
}

extern "C" void kernel_launch(void* const* d_in, const int* in_sizes, int n_in,
                              void* d_out, int out_size)
{
    (void)in_sizes; (void)n_in; (void)out_size;
    Params P;
    P.obs = (const float*)d_in[0];
    P.Wp1 = (const float*)d_in[1];  P.bp1 = (const float*)d_in[2];
    P.Ws1 = (const float*)d_in[3];  P.Wn1 = (const float*)d_in[4];
    P.b1  = (const float*)d_in[5];
    P.Wp2 = (const float*)d_in[6];  P.bp2 = (const float*)d_in[7];
    P.Ws2 = (const float*)d_in[8];  P.Wn2 = (const float*)d_in[9];
    P.b2  = (const float*)d_in[10];
    P.MW1 = (const float*)d_in[11]; P.Mb1 = (const float*)d_in[12];
    P.MW2 = (const float*)d_in[13]; P.Mb2 = (const float*)d_in[14];
    P.MW3 = (const float*)d_in[15]; P.Mb3 = (const float*)d_in[16];
    P.MW4 = (const float*)d_in[17]; P.Mb4 = (const float*)d_in[18];
    P.out = (float*)d_out;

    int dev = 0, nsm = 148;
    cudaGetDevice(&dev);
    cudaDeviceGetAttribute(&nsm, cudaDevAttrMultiProcessorCount, dev);

    // groups per warp, multiple of 4 (MLP ring size)
    int nw = nsm * WARPS;
    int ch4 = ((G_TOT + nw * 4 - 1) / (nw * 4)) * 4;
    P.ch4 = ch4;

    prep_kernel<<<(8 * 1024 + 255) / 256, 256>>>(P.Wn1, P.Wn2, P.MW1, P.MW2, P.MW3);

    cudaFuncSetAttribute(gnn_kernel, cudaFuncAttributeMaxDynamicSharedMemorySize,
                         SMEM_BYTES);
    gnn_kernel<<<nsm, THREADS, SMEM_BYTES>>>(P);
}